// round 3
// baseline (speedup 1.0000x reference)
#include <cuda_runtime.h>
#include <math.h>

#define N_NODES 50000
#define N_EDGES 800000
#define MUL 32
#define RAD 8
#define FC 64
#define TILE 32
#define EDGE_BLOCKS 592
#define N_TILES (N_EDGES / TILE)

typedef unsigned long long u64;

// ---------------- scratch (static device globals; no allocation) ----------------
__device__ __align__(16) float g_f0[N_NODES * MUL];          // 6.4 MB
__device__ __align__(16) float g_self0[N_NODES * MUL];       // 6.4 MB
__device__ __align__(16) float g_f1[N_NODES * MUL * 3];      // 19.2 MB
__device__ __align__(16) float g_self1[N_NODES * MUL * 3];   // 19.2 MB
__device__ __align__(16) float g_n0[N_NODES * 2 * MUL];      // 12.8 MB
__device__ __align__(16) float g_n1[N_NODES * 2 * MUL * 3];  // 38.4 MB

__device__ __forceinline__ float gelu_f(float x) {
    float u = 0.7978845608028654f * fmaf(0.044715f * x, x * x, x);
    float t;
    asm("tanh.approx.f32 %0, %1;" : "=f"(t) : "f"(u));
    return 0.5f * x * (1.0f + t);
}

// ---- packed fp32x2 helpers (Blackwell FFMA2; exact fp32 semantics) ----
__device__ __forceinline__ u64 splat2(float v) {
    u64 r; asm("mov.b64 %0, {%1, %1};" : "=l"(r) : "f"(v)); return r;
}
__device__ __forceinline__ u64 ffma2(u64 a, u64 b, u64 c) {
    u64 d; asm("fma.rn.f32x2 %0, %1, %2, %3;" : "=l"(d) : "l"(a), "l"(b), "l"(c)); return d;
}
__device__ __forceinline__ float2 unpk2(u64 v) {
    float2 f; asm("mov.b64 {%0, %1}, %2;" : "=f"(f.x), "=f"(f.y) : "l"(v)); return f;
}

__device__ __forceinline__ void red_add_v4(float* addr, float a, float b, float c, float d) {
    asm volatile("red.global.add.v4.f32 [%0], {%1,%2,%3,%4};"
                 :: "l"(addr), "f"(a), "f"(b), "f"(c), "f"(d) : "memory");
}

// ---------------- kernel 0: zero accumulators ----------------
__global__ void zero_acc_kernel() {
    int i = blockIdx.x * blockDim.x + threadIdx.x;
    float4 z = make_float4(0.f, 0.f, 0.f, 0.f);
    if (i < N_NODES * 16) reinterpret_cast<float4*>(g_n0)[i] = z;
    if (i < N_NODES * 48) reinterpret_cast<float4*>(g_n1)[i] = z;
}

// ---------------- kernel 1: node pre-transform ----------------
__global__ __launch_bounds__(128) void node_transform_kernel(
    const float* __restrict__ node_s, const float* __restrict__ node_v,
    const float* __restrict__ Wf0, const float* __restrict__ Ws0,
    const float* __restrict__ Wf1, const float* __restrict__ Ws1)
{
    __shared__ float sWf0[MUL * MUL], sWs0[MUL * MUL], sWf1[MUL * MUL], sWs1[MUL * MUL];
    __shared__ float sS[4][MUL];
    __shared__ float sV[4][MUL * 3];
    int t = threadIdx.x;
    for (int i = t; i < MUL * MUL; i += 128) {
        sWf0[i] = Wf0[i]; sWs0[i] = Ws0[i]; sWf1[i] = Wf1[i]; sWs1[i] = Ws1[i];
    }
    int node0 = blockIdx.x * 4;
    int ni = t >> 5, j = t & 31;
    int n = node0 + ni;
    sS[ni][j] = node_s[n * MUL + j];
#pragma unroll
    for (int i = 0; i < 3; i++) sV[ni][j * 3 + i] = node_v[n * MUL * 3 + j * 3 + i];
    __syncthreads();

    float a0 = 0.f, b0 = 0.f;
    float a1x = 0.f, a1y = 0.f, a1z = 0.f, b1x = 0.f, b1y = 0.f, b1z = 0.f;
#pragma unroll
    for (int u = 0; u < MUL; ++u) {
        float su = sS[ni][u];
        float vx = sV[ni][u * 3 + 0], vy = sV[ni][u * 3 + 1], vz = sV[ni][u * 3 + 2];
        float wf0 = sWf0[u * MUL + j], ws0 = sWs0[u * MUL + j];
        float wf1 = sWf1[u * MUL + j], ws1 = sWs1[u * MUL + j];
        a0 += su * wf0;  b0 += su * ws0;
        a1x += vx * wf1; a1y += vy * wf1; a1z += vz * wf1;
        b1x += vx * ws1; b1y += vy * ws1; b1z += vz * ws1;
    }
    const float ism = 0.17677669529663687f;
    g_f0[n * MUL + j]    = a0 * ism;
    g_self0[n * MUL + j] = b0 * ism;
    int vb = (n * MUL + j) * 3;
    g_f1[vb + 0] = a1x * ism; g_f1[vb + 1] = a1y * ism; g_f1[vb + 2] = a1z * ism;
    g_self1[vb + 0] = b1x * ism; g_self1[vb + 1] = b1y * ism; g_self1[vb + 2] = b1z * ism;
}

// ---------------- kernel 2: edge MLP + tensor product + scatter ----------------
// smem layout identical to round 2 (conflict-free padded k-major weights)
#define EDGE_SMEM_FLOATS 21760
#define EDGE_SMEM_BYTES  (EDGE_SMEM_FLOATS * 4)

__global__ __launch_bounds__(128, 2) void edge_kernel(
    const float* __restrict__ sh0, const float* __restrict__ sh1,
    const float* __restrict__ edge_scalar,
    const int* __restrict__ edge_src, const int* __restrict__ edge_dst,
    const float* __restrict__ mlp_w0, const float* __restrict__ mlp_w1,
    const float* __restrict__ wp0, const float* __restrict__ wp1,
    const float* __restrict__ wp2, const float* __restrict__ wp3)
{
    extern __shared__ float smem[];
    float* sW0  = smem;            // [8][64]
    float* sW1v = smem + 512;      // [16][260]
    float* sWPv = smem + 4672;     // [16][516]
    float* sH1  = smem + 12928;    // [32][68]
    float* sH2  = smem + 15104;    // [32][68]
    float* sWW  = smem + 17280;    // [32][132]
    float* sES  = smem + 21504;    // [32][8]

    int t = threadIdx.x;

    for (int i = t; i < RAD * FC; i += 128) sW0[i] = mlp_w0[i];
    for (int i = t; i < FC * FC; i += 128) {
        int k = i >> 6, j = i & 63;
        sW1v[(j >> 2) * 260 + k * 4 + (j & 3)] = mlp_w1[i];
    }
    for (int i = t; i < FC * MUL; i += 128) {
        int k = i >> 5, m = i & 31;
        int c;
        c = m;      sWPv[(c >> 3) * 516 + k * 8 + (c & 7)] = wp0[i];
        c = 32 + m; sWPv[(c >> 3) * 516 + k * 8 + (c & 7)] = wp1[i];
        c = 64 + m; sWPv[(c >> 3) * 516 + k * 8 + (c & 7)] = wp2[i];
        c = 96 + m; sWPv[(c >> 3) * 516 + k * 8 + (c & 7)] = wp3[i];
    }

    const float isr = 0.35355339059327373f; // 1/sqrt(8)
    const float isf = 0.125f;               // 1/sqrt(64)

    int et = t >> 4, jt = t & 15;
    int e4 = t >> 2, q4 = t & 3;
    int u0 = q4 * 8;

    for (int tile = blockIdx.x; tile < N_TILES; tile += gridDim.x) {
        int ebase = tile * TILE;

        // ---- prefetch stage-4 operands (hidden behind MLP compute) ----
        int src = edge_src[ebase + e4];
        int dst = edge_dst[ebase + e4];
        float s0  = sh0[ebase + e4];
        float s1x = sh1[(ebase + e4) * 3 + 0];
        float s1y = sh1[(ebase + e4) * 3 + 1];
        float s1z = sh1[(ebase + e4) * 3 + 2];
        float4 F0a = *(const float4*)&g_f0[src * 32 + u0];
        float4 F0b = *(const float4*)&g_f0[src * 32 + u0 + 4];
        float4 F1[6];
        {
            const float4* p = (const float4*)&g_f1[src * 96 + u0 * 3];
#pragma unroll
            for (int i = 0; i < 6; i++) F1[i] = p[i];
        }

        for (int i = t; i < TILE * RAD; i += 128) sES[i] = edge_scalar[ebase * RAD + i];
        __syncthreads();

        // ---- stage 1: H1 = gelu(ES @ W0 * isr)  packed f32x2 ----
        {
            u64 acc[4][2];
#pragma unroll
            for (int x = 0; x < 4; x++) { acc[x][0] = 0ULL; acc[x][1] = 0ULL; }
#pragma unroll
            for (int k = 0; k < RAD; k++) {
                ulonglong2 b = *(const ulonglong2*)&sW0[k * 64 + jt * 4];
#pragma unroll
                for (int x = 0; x < 4; x++) {
                    u64 as = splat2(sES[(et * 4 + x) * 8 + k]);
                    acc[x][0] = ffma2(as, b.x, acc[x][0]);
                    acc[x][1] = ffma2(as, b.y, acc[x][1]);
                }
            }
#pragma unroll
            for (int x = 0; x < 4; x++) {
                float2 lo = unpk2(acc[x][0]), hi = unpk2(acc[x][1]);
                float* row = &sH1[(et * 4 + x) * 68 + jt * 4];
                row[0] = gelu_f(lo.x * isr); row[1] = gelu_f(lo.y * isr);
                row[2] = gelu_f(hi.x * isr); row[3] = gelu_f(hi.y * isr);
            }
        }
        __syncthreads();

        // ---- stage 2: H2 = gelu(H1 @ W1 * isf)  packed f32x2, K=64 ----
        {
            u64 acc[4][2];
#pragma unroll
            for (int x = 0; x < 4; x++) { acc[x][0] = 0ULL; acc[x][1] = 0ULL; }
#pragma unroll 4
            for (int kk = 0; kk < FC; kk += 4) {
                float4 a[4];
#pragma unroll
                for (int x = 0; x < 4; x++)
                    a[x] = *(const float4*)&sH1[(et * 4 + x) * 68 + kk];
                ulonglong2 b0 = *(const ulonglong2*)&sW1v[jt * 260 + (kk + 0) * 4];
                ulonglong2 b1 = *(const ulonglong2*)&sW1v[jt * 260 + (kk + 1) * 4];
                ulonglong2 b2 = *(const ulonglong2*)&sW1v[jt * 260 + (kk + 2) * 4];
                ulonglong2 b3 = *(const ulonglong2*)&sW1v[jt * 260 + (kk + 3) * 4];
#pragma unroll
                for (int x = 0; x < 4; x++) {
                    u64 a0 = splat2(a[x].x), a1 = splat2(a[x].y);
                    u64 a2 = splat2(a[x].z), a3 = splat2(a[x].w);
                    acc[x][0] = ffma2(a0, b0.x, acc[x][0]);
                    acc[x][1] = ffma2(a0, b0.y, acc[x][1]);
                    acc[x][0] = ffma2(a1, b1.x, acc[x][0]);
                    acc[x][1] = ffma2(a1, b1.y, acc[x][1]);
                    acc[x][0] = ffma2(a2, b2.x, acc[x][0]);
                    acc[x][1] = ffma2(a2, b2.y, acc[x][1]);
                    acc[x][0] = ffma2(a3, b3.x, acc[x][0]);
                    acc[x][1] = ffma2(a3, b3.y, acc[x][1]);
                }
            }
#pragma unroll
            for (int x = 0; x < 4; x++) {
                float2 lo = unpk2(acc[x][0]), hi = unpk2(acc[x][1]);
                float* row = &sH2[(et * 4 + x) * 68 + jt * 4];
                row[0] = gelu_f(lo.x * isf); row[1] = gelu_f(lo.y * isf);
                row[2] = gelu_f(hi.x * isf); row[3] = gelu_f(hi.y * isf);
            }
        }
        __syncthreads();

        // ---- stage 3: W = H2 @ [wp0..wp3] * isf  packed f32x2, K=64, 8 cols ----
        {
            u64 acc[4][4];
#pragma unroll
            for (int x = 0; x < 4; x++)
#pragma unroll
                for (int y = 0; y < 4; y++) acc[x][y] = 0ULL;
#pragma unroll 4
            for (int kk = 0; kk < FC; kk += 4) {
                float4 a[4];
#pragma unroll
                for (int x = 0; x < 4; x++)
                    a[x] = *(const float4*)&sH2[(et * 4 + x) * 68 + kk];
#pragma unroll
                for (int dk = 0; dk < 4; dk++) {
                    ulonglong2 c0 = *(const ulonglong2*)&sWPv[jt * 516 + (kk + dk) * 8];
                    ulonglong2 c1 = *(const ulonglong2*)&sWPv[jt * 516 + (kk + dk) * 8 + 4];
#pragma unroll
                    for (int x = 0; x < 4; x++) {
                        float av = (dk == 0) ? a[x].x : (dk == 1) ? a[x].y : (dk == 2) ? a[x].z : a[x].w;
                        u64 as = splat2(av);
                        acc[x][0] = ffma2(as, c0.x, acc[x][0]);
                        acc[x][1] = ffma2(as, c0.y, acc[x][1]);
                        acc[x][2] = ffma2(as, c1.x, acc[x][2]);
                        acc[x][3] = ffma2(as, c1.y, acc[x][3]);
                    }
                }
            }
#pragma unroll
            for (int x = 0; x < 4; x++) {
                float2 p0 = unpk2(acc[x][0]), p1 = unpk2(acc[x][1]);
                float2 p2 = unpk2(acc[x][2]), p3 = unpk2(acc[x][3]);
                float4 v0 = make_float4(p0.x * isf, p0.y * isf, p1.x * isf, p1.y * isf);
                float4 v1 = make_float4(p2.x * isf, p2.y * isf, p3.x * isf, p3.y * isf);
                *(float4*)&sWW[(et * 4 + x) * 132 + jt * 8]     = v0;
                *(float4*)&sWW[(et * 4 + x) * 132 + jt * 8 + 4] = v1;
            }
        }
        __syncthreads();

        // ---- stage 4: tensor product + v4-red scatter ----
        {
            float e0v[8];
            e0v[0] = F0a.x; e0v[1] = F0a.y; e0v[2] = F0a.z; e0v[3] = F0a.w;
            e0v[4] = F0b.x; e0v[5] = F0b.y; e0v[6] = F0b.z; e0v[7] = F0b.w;
            float e1v[24];
#pragma unroll
            for (int i = 0; i < 6; i++) {
                e1v[4 * i + 0] = F1[i].x; e1v[4 * i + 1] = F1[i].y;
                e1v[4 * i + 2] = F1[i].z; e1v[4 * i + 3] = F1[i].w;
            }
            float w0v[8], w1v[8], w2v[8], w3v[8];
#pragma unroll
            for (int x = 0; x < 8; x += 4) {
                float4 v;
                v = *(const float4*)&sWW[e4 * 132 + 0  + u0 + x]; w0v[x] = v.x; w0v[x+1] = v.y; w0v[x+2] = v.z; w0v[x+3] = v.w;
                v = *(const float4*)&sWW[e4 * 132 + 32 + u0 + x]; w1v[x] = v.x; w1v[x+1] = v.y; w1v[x+2] = v.z; w1v[x+3] = v.w;
                v = *(const float4*)&sWW[e4 * 132 + 64 + u0 + x]; w2v[x] = v.x; w2v[x+1] = v.y; w2v[x+2] = v.z; w2v[x+3] = v.w;
                v = *(const float4*)&sWW[e4 * 132 + 96 + u0 + x]; w3v[x] = v.x; w3v[x+1] = v.y; w3v[x+2] = v.z; w3v[x+3] = v.w;
            }
            const float inn = 0.25f;
            const float k3  = 0.5773502691896258f * 0.25f;
            float p0[8], p3[8], p1[24], p2[24];
#pragma unroll
            for (int x = 0; x < 8; x++) {
                float e0u = e0v[x];
                float ex = e1v[3 * x + 0], ey = e1v[3 * x + 1], ez = e1v[3 * x + 2];
                p0[x] = w0v[x] * e0u * s0 * inn;
                p3[x] = w3v[x] * (ex * s1x + ey * s1y + ez * s1z) * k3;
                float w1e = w1v[x] * e0u * inn;
                p1[3 * x + 0] = w1e * s1x; p1[3 * x + 1] = w1e * s1y; p1[3 * x + 2] = w1e * s1z;
                float w2s = w2v[x] * s0 * inn;
                p2[3 * x + 0] = w2s * ex; p2[3 * x + 1] = w2s * ey; p2[3 * x + 2] = w2s * ez;
            }
            float* n0a = &g_n0[dst * 64 + u0];
            red_add_v4(n0a,     p0[0], p0[1], p0[2], p0[3]);
            red_add_v4(n0a + 4, p0[4], p0[5], p0[6], p0[7]);
            float* n0b = &g_n0[dst * 64 + 32 + u0];
            red_add_v4(n0b,     p3[0], p3[1], p3[2], p3[3]);
            red_add_v4(n0b + 4, p3[4], p3[5], p3[6], p3[7]);
            float* n1a = &g_n1[dst * 192 + u0 * 3];
#pragma unroll
            for (int i = 0; i < 6; i++)
                red_add_v4(n1a + 4 * i, p1[4 * i], p1[4 * i + 1], p1[4 * i + 2], p1[4 * i + 3]);
            float* n1b = &g_n1[dst * 192 + 96 + u0 * 3];
#pragma unroll
            for (int i = 0; i < 6; i++)
                red_add_v4(n1b + 4 * i, p2[4 * i], p2[4 * i + 1], p2[4 * i + 2], p2[4 * i + 3]);
        }
        __syncthreads(); // protect sWW/sES before next tile overwrites
    }
}

// ---------------- kernel 3: output transform (vectorized LDS) ----------------
__global__ __launch_bounds__(128) void output_kernel(
    const float* __restrict__ Wout0, const float* __restrict__ Wout1,
    float* __restrict__ out)
{
    __shared__ float sW0T[32 * 68], sW1T[32 * 68];  // j-major transposed, pad 4
    __shared__ float sN0[4][64];
    __shared__ float sN1[4][192];
    int t = threadIdx.x;
    // W_out is [64][32] (u rows, j cols) -> sWT[j*68 + u]
    for (int i = t; i < FC * MUL; i += 128) {
        int u = i >> 5, j = i & 31;
        sW0T[j * 68 + u] = Wout0[i];
        sW1T[j * 68 + u] = Wout1[i];
    }
    int node0 = blockIdx.x * 4;
    for (int i = t; i < 4 * 16; i += 128)
        ((float4*)sN0)[i] = ((const float4*)&g_n0[node0 * 64])[i];
    for (int i = t; i < 4 * 48; i += 128)
        ((float4*)sN1)[i] = ((const float4*)&g_n1[node0 * 192])[i];
    __syncthreads();

    int ni = t >> 5, j = t & 31;
    int n = node0 + ni;
    float c0 = 0.f, c1x = 0.f, c1y = 0.f, c1z = 0.f;
#pragma unroll
    for (int u = 0; u < FC; u += 4) {
        float4 w0 = *(const float4*)&sW0T[j * 68 + u];
        float4 n0 = *(const float4*)&sN0[ni][u];
        c0 = fmaf(w0.x, n0.x, fmaf(w0.y, n0.y, fmaf(w0.z, n0.z, fmaf(w0.w, n0.w, c0))));
        float4 w1 = *(const float4*)&sW1T[j * 68 + u];
        float4 v0 = *(const float4*)&sN1[ni][u * 3];
        float4 v1 = *(const float4*)&sN1[ni][u * 3 + 4];
        float4 v2 = *(const float4*)&sN1[ni][u * 3 + 8];
        c1x = fmaf(w1.x, v0.x, fmaf(w1.y, v0.w, fmaf(w1.z, v1.z, fmaf(w1.w, v2.y, c1x))));
        c1y = fmaf(w1.x, v0.y, fmaf(w1.y, v1.x, fmaf(w1.z, v1.w, fmaf(w1.w, v2.z, c1y))));
        c1z = fmaf(w1.x, v0.z, fmaf(w1.y, v1.y, fmaf(w1.z, v2.x, fmaf(w1.w, v2.w, c1z))));
    }
    const float i2m = 0.125f;
    const float cc = 0.9238795325112867f;
    const float ss = 0.3826834323650898f;
    int vb = (n * 32 + j) * 3;
    float o0  = cc * g_self0[n * 32 + j] + ss * c0 * i2m;
    float o1x = cc * g_self1[vb + 0] + ss * c1x * i2m;
    float o1y = cc * g_self1[vb + 1] + ss * c1y * i2m;
    float o1z = cc * g_self1[vb + 2] + ss * c1z * i2m;
    out[n * 128 + j] = o0;
    out[n * 128 + 32 + j * 3 + 0] = o1x;
    out[n * 128 + 32 + j * 3 + 1] = o1y;
    out[n * 128 + 32 + j * 3 + 2] = o1z;
}

// ---------------- host launcher ----------------
extern "C" void kernel_launch(void* const* d_in, const int* in_sizes, int n_in,
                              void* d_out, int out_size)
{
    const float* node_s      = (const float*)d_in[0];
    const float* node_v      = (const float*)d_in[1];
    const float* sh0         = (const float*)d_in[2];
    const float* sh1         = (const float*)d_in[3];
    const float* edge_scalar = (const float*)d_in[4];
    const int*   edge_src    = (const int*)d_in[5];
    const int*   edge_dst    = (const int*)d_in[6];
    const float* W_feat0     = (const float*)d_in[7];
    const float* W_self0     = (const float*)d_in[8];
    const float* W_feat1     = (const float*)d_in[9];
    const float* W_self1     = (const float*)d_in[10];
    const float* mlp_w0      = (const float*)d_in[11];
    const float* mlp_w1      = (const float*)d_in[12];
    const float* wp0         = (const float*)d_in[13];
    const float* wp1         = (const float*)d_in[14];
    const float* wp2         = (const float*)d_in[15];
    const float* wp3         = (const float*)d_in[16];
    const float* W_out0      = (const float*)d_in[17];
    const float* W_out1      = (const float*)d_in[18];
    float* out = (float*)d_out;

    cudaFuncSetAttribute(edge_kernel, cudaFuncAttributeMaxDynamicSharedMemorySize,
                         EDGE_SMEM_BYTES);

    zero_acc_kernel<<<(N_NODES * 48 + 255) / 256, 256>>>();

    node_transform_kernel<<<N_NODES / 4, 128>>>(node_s, node_v,
                                                W_feat0, W_self0, W_feat1, W_self1);

    edge_kernel<<<EDGE_BLOCKS, 128, EDGE_SMEM_BYTES>>>(
        sh0, sh1, edge_scalar, edge_src, edge_dst,
        mlp_w0, mlp_w1, wp0, wp1, wp2, wp3);

    output_kernel<<<N_NODES / 4, 128>>>(W_out0, W_out1, out);
}

// round 4
// speedup vs baseline: 1.2415x; 1.2415x over previous
#include <cuda_runtime.h>
#include <math.h>

#define N_NODES 50000
#define N_EDGES 800000
#define MUL 32
#define RAD 8
#define FC 64
#define EDGE_BLOCKS 148
#define N_GROUPS (N_EDGES / 8)   // 8 edges per warp-group

typedef unsigned long long u64;

// ---------------- scratch (static device globals; no allocation) ----------------
__device__ __align__(16) float g_f0[N_NODES * MUL];
__device__ __align__(16) float g_self0[N_NODES * MUL];
__device__ __align__(16) float g_f1[N_NODES * MUL * 3];
__device__ __align__(16) float g_self1[N_NODES * MUL * 3];
__device__ __align__(16) float g_n0[N_NODES * 2 * MUL];
__device__ __align__(16) float g_n1[N_NODES * 2 * MUL * 3];

__device__ __forceinline__ float gelu_f(float x) {
    float u = 0.7978845608028654f * fmaf(0.044715f * x, x * x, x);
    float t;
    asm("tanh.approx.f32 %0, %1;" : "=f"(t) : "f"(u));
    return 0.5f * x * (1.0f + t);
}

__device__ __forceinline__ u64 splat2(float v) {
    u64 r; asm("mov.b64 %0, {%1, %1};" : "=l"(r) : "f"(v)); return r;
}
__device__ __forceinline__ u64 ffma2(u64 a, u64 b, u64 c) {
    u64 d; asm("fma.rn.f32x2 %0, %1, %2, %3;" : "=l"(d) : "l"(a), "l"(b), "l"(c)); return d;
}
__device__ __forceinline__ float2 unpk2(u64 v) {
    float2 f; asm("mov.b64 {%0, %1}, %2;" : "=f"(f.x), "=f"(f.y) : "l"(v)); return f;
}

__device__ __forceinline__ void red_add_v4(float* addr, float a, float b, float c, float d) {
    asm volatile("red.global.add.v4.f32 [%0], {%1,%2,%3,%4};"
                 :: "l"(addr), "f"(a), "f"(b), "f"(c), "f"(d) : "memory");
}

// ---------------- kernel 0: zero accumulators ----------------
__global__ void zero_acc_kernel() {
    int i = blockIdx.x * blockDim.x + threadIdx.x;
    float4 z = make_float4(0.f, 0.f, 0.f, 0.f);
    if (i < N_NODES * 16) reinterpret_cast<float4*>(g_n0)[i] = z;
    if (i < N_NODES * 48) reinterpret_cast<float4*>(g_n1)[i] = z;
}

// ---------------- kernel 1: node pre-transform ----------------
__global__ __launch_bounds__(128) void node_transform_kernel(
    const float* __restrict__ node_s, const float* __restrict__ node_v,
    const float* __restrict__ Wf0, const float* __restrict__ Ws0,
    const float* __restrict__ Wf1, const float* __restrict__ Ws1)
{
    __shared__ float sWf0[MUL * MUL], sWs0[MUL * MUL], sWf1[MUL * MUL], sWs1[MUL * MUL];
    __shared__ float sS[4][MUL];
    __shared__ float sV[4][MUL * 3];
    int t = threadIdx.x;
    for (int i = t; i < MUL * MUL; i += 128) {
        sWf0[i] = Wf0[i]; sWs0[i] = Ws0[i]; sWf1[i] = Wf1[i]; sWs1[i] = Ws1[i];
    }
    int node0 = blockIdx.x * 4;
    int ni = t >> 5, j = t & 31;
    int n = node0 + ni;
    sS[ni][j] = node_s[n * MUL + j];
#pragma unroll
    for (int i = 0; i < 3; i++) sV[ni][j * 3 + i] = node_v[n * MUL * 3 + j * 3 + i];
    __syncthreads();

    float a0 = 0.f, b0 = 0.f;
    float a1x = 0.f, a1y = 0.f, a1z = 0.f, b1x = 0.f, b1y = 0.f, b1z = 0.f;
#pragma unroll
    for (int u = 0; u < MUL; ++u) {
        float su = sS[ni][u];
        float vx = sV[ni][u * 3 + 0], vy = sV[ni][u * 3 + 1], vz = sV[ni][u * 3 + 2];
        float wf0 = sWf0[u * MUL + j], ws0 = sWs0[u * MUL + j];
        float wf1 = sWf1[u * MUL + j], ws1 = sWs1[u * MUL + j];
        a0 += su * wf0;  b0 += su * ws0;
        a1x += vx * wf1; a1y += vy * wf1; a1z += vz * wf1;
        b1x += vx * ws1; b1y += vy * ws1; b1z += vz * ws1;
    }
    const float ism = 0.17677669529663687f;
    g_f0[n * MUL + j]    = a0 * ism;
    g_self0[n * MUL + j] = b0 * ism;
    int vb = (n * MUL + j) * 3;
    g_f1[vb + 0] = a1x * ism; g_f1[vb + 1] = a1y * ism; g_f1[vb + 2] = a1z * ism;
    g_self1[vb + 0] = b1x * ism; g_self1[vb + 1] = b1y * ism; g_self1[vb + 2] = b1z * ism;
}

// ---------------- kernel 2: edge pipeline, 16 independent warps per CTA ----------------
// smem (floats):
//   weights: sW0 [8][64] @0 (512) ; sW1v [16][260] @512 (4160) ; sWPv [16][516] @4672 (8256)
//   per-warp slice @12928 + wid*2208:
//     sH1 [8][68] (544) ; sH2 [8][68] (544) ; sWW [8][132] (1056) ; sES [8][8] (64)
#define EDGE_SMEM_FLOATS (12928 + 16 * 2208)
#define EDGE_SMEM_BYTES  (EDGE_SMEM_FLOATS * 4)

__global__ __launch_bounds__(512, 1) void edge_kernel(
    const float* __restrict__ sh0, const float* __restrict__ sh1,
    const float* __restrict__ edge_scalar,
    const int* __restrict__ edge_src, const int* __restrict__ edge_dst,
    const float* __restrict__ mlp_w0, const float* __restrict__ mlp_w1,
    const float* __restrict__ wp0, const float* __restrict__ wp1,
    const float* __restrict__ wp2, const float* __restrict__ wp3)
{
    extern __shared__ float smem[];
    float* sW0  = smem;
    float* sW1v = smem + 512;
    float* sWPv = smem + 4672;

    int t = threadIdx.x;
    int wid = t >> 5, lane = t & 31;

    // ---- load weights once per block ----
    for (int i = t; i < RAD * FC; i += 512) sW0[i] = mlp_w0[i];
    for (int i = t; i < FC * FC; i += 512) {
        int k = i >> 6, j = i & 63;
        sW1v[(j >> 2) * 260 + k * 4 + (j & 3)] = mlp_w1[i];
    }
    for (int i = t; i < FC * MUL; i += 512) {
        int k = i >> 5, m = i & 31;
        int c;
        c = m;      sWPv[(c >> 3) * 516 + k * 8 + (c & 7)] = wp0[i];
        c = 32 + m; sWPv[(c >> 3) * 516 + k * 8 + (c & 7)] = wp1[i];
        c = 64 + m; sWPv[(c >> 3) * 516 + k * 8 + (c & 7)] = wp2[i];
        c = 96 + m; sWPv[(c >> 3) * 516 + k * 8 + (c & 7)] = wp3[i];
    }
    __syncthreads();

    float* sWarp = smem + 12928 + wid * 2208;
    float* sH1 = sWarp;
    float* sH2 = sWarp + 544;
    float* sWW = sWarp + 1088;
    float* sES = sWarp + 2144;

    const float isr = 0.35355339059327373f; // 1/sqrt(8)
    const float isf = 0.125f;               // 1/sqrt(64)

    int el = lane >> 4, jl = lane & 15;      // stages 1-3: edge group (4), col group
    int e4 = lane >> 2, q4 = lane & 3;       // stage 4: edge, quarter
    int u0 = q4 * 8;

    int gw = blockIdx.x * 16 + wid;
    int nw = gridDim.x * 16;

    for (int g = gw; g < N_GROUPS; g += nw) {
        int ebase = g * 8;

        // ---- load per-edge scalars (coalesced) + prefetch gathers ----
        *(float2*)&sES[lane * 2] = *(const float2*)&edge_scalar[ebase * RAD + lane * 2];

        int eg = ebase + e4;
        int src = edge_src[eg];
        int dst = edge_dst[eg];
        float s0  = sh0[eg];
        float s1x = sh1[eg * 3 + 0];
        float s1y = sh1[eg * 3 + 1];
        float s1z = sh1[eg * 3 + 2];
        float4 F0a = *(const float4*)&g_f0[src * 32 + u0];
        float4 F0b = *(const float4*)&g_f0[src * 32 + u0 + 4];
        float4 F1[6];
        {
            const float4* p = (const float4*)&g_f1[src * 96 + u0 * 3];
#pragma unroll
            for (int i = 0; i < 6; i++) F1[i] = p[i];
        }
        __syncwarp();

        // ---- stage 1: H1 = gelu(ES @ W0 * isr)  (8e x 64j, K=8) ----
        {
            u64 acc[4][2];
#pragma unroll
            for (int x = 0; x < 4; x++) { acc[x][0] = 0ULL; acc[x][1] = 0ULL; }
#pragma unroll
            for (int k = 0; k < RAD; k++) {
                ulonglong2 b = *(const ulonglong2*)&sW0[k * 64 + jl * 4];
#pragma unroll
                for (int x = 0; x < 4; x++) {
                    u64 as = splat2(sES[(el * 4 + x) * 8 + k]);
                    acc[x][0] = ffma2(as, b.x, acc[x][0]);
                    acc[x][1] = ffma2(as, b.y, acc[x][1]);
                }
            }
#pragma unroll
            for (int x = 0; x < 4; x++) {
                float2 lo = unpk2(acc[x][0]), hi = unpk2(acc[x][1]);
                float* row = &sH1[(el * 4 + x) * 68 + jl * 4];
                row[0] = gelu_f(lo.x * isr); row[1] = gelu_f(lo.y * isr);
                row[2] = gelu_f(hi.x * isr); row[3] = gelu_f(hi.y * isr);
            }
        }
        __syncwarp();

        // ---- stage 2: H2 = gelu(H1 @ W1 * isf)  (8e x 64j, K=64) ----
        {
            u64 acc[4][2];
#pragma unroll
            for (int x = 0; x < 4; x++) { acc[x][0] = 0ULL; acc[x][1] = 0ULL; }
#pragma unroll 4
            for (int kk = 0; kk < FC; kk += 4) {
                float4 a[4];
#pragma unroll
                for (int x = 0; x < 4; x++)
                    a[x] = *(const float4*)&sH1[(el * 4 + x) * 68 + kk];
                ulonglong2 b0 = *(const ulonglong2*)&sW1v[jl * 260 + (kk + 0) * 4];
                ulonglong2 b1 = *(const ulonglong2*)&sW1v[jl * 260 + (kk + 1) * 4];
                ulonglong2 b2 = *(const ulonglong2*)&sW1v[jl * 260 + (kk + 2) * 4];
                ulonglong2 b3 = *(const ulonglong2*)&sW1v[jl * 260 + (kk + 3) * 4];
#pragma unroll
                for (int x = 0; x < 4; x++) {
                    u64 a0 = splat2(a[x].x), a1 = splat2(a[x].y);
                    u64 a2 = splat2(a[x].z), a3 = splat2(a[x].w);
                    acc[x][0] = ffma2(a0, b0.x, acc[x][0]);
                    acc[x][1] = ffma2(a0, b0.y, acc[x][1]);
                    acc[x][0] = ffma2(a1, b1.x, acc[x][0]);
                    acc[x][1] = ffma2(a1, b1.y, acc[x][1]);
                    acc[x][0] = ffma2(a2, b2.x, acc[x][0]);
                    acc[x][1] = ffma2(a2, b2.y, acc[x][1]);
                    acc[x][0] = ffma2(a3, b3.x, acc[x][0]);
                    acc[x][1] = ffma2(a3, b3.y, acc[x][1]);
                }
            }
#pragma unroll
            for (int x = 0; x < 4; x++) {
                float2 lo = unpk2(acc[x][0]), hi = unpk2(acc[x][1]);
                float* row = &sH2[(el * 4 + x) * 68 + jl * 4];
                row[0] = gelu_f(lo.x * isf); row[1] = gelu_f(lo.y * isf);
                row[2] = gelu_f(hi.x * isf); row[3] = gelu_f(hi.y * isf);
            }
        }
        __syncwarp();

        // ---- stage 3: W = H2 @ [wp0..wp3] * isf  (8e x 128m, K=64) ----
        {
            u64 acc[4][4];
#pragma unroll
            for (int x = 0; x < 4; x++)
#pragma unroll
                for (int y = 0; y < 4; y++) acc[x][y] = 0ULL;
#pragma unroll 4
            for (int kk = 0; kk < FC; kk += 4) {
                float4 a[4];
#pragma unroll
                for (int x = 0; x < 4; x++)
                    a[x] = *(const float4*)&sH2[(el * 4 + x) * 68 + kk];
#pragma unroll
                for (int dk = 0; dk < 4; dk++) {
                    ulonglong2 c0 = *(const ulonglong2*)&sWPv[jl * 516 + (kk + dk) * 8];
                    ulonglong2 c1 = *(const ulonglong2*)&sWPv[jl * 516 + (kk + dk) * 8 + 4];
#pragma unroll
                    for (int x = 0; x < 4; x++) {
                        float av = (dk == 0) ? a[x].x : (dk == 1) ? a[x].y : (dk == 2) ? a[x].z : a[x].w;
                        u64 as = splat2(av);
                        acc[x][0] = ffma2(as, c0.x, acc[x][0]);
                        acc[x][1] = ffma2(as, c0.y, acc[x][1]);
                        acc[x][2] = ffma2(as, c1.x, acc[x][2]);
                        acc[x][3] = ffma2(as, c1.y, acc[x][3]);
                    }
                }
            }
#pragma unroll
            for (int x = 0; x < 4; x++) {
                float2 p0 = unpk2(acc[x][0]), p1 = unpk2(acc[x][1]);
                float2 p2 = unpk2(acc[x][2]), p3 = unpk2(acc[x][3]);
                float4 v0 = make_float4(p0.x * isf, p0.y * isf, p1.x * isf, p1.y * isf);
                float4 v1 = make_float4(p2.x * isf, p2.y * isf, p3.x * isf, p3.y * isf);
                *(float4*)&sWW[(el * 4 + x) * 132 + jl * 8]     = v0;
                *(float4*)&sWW[(el * 4 + x) * 132 + jl * 8 + 4] = v1;
            }
        }
        __syncwarp();

        // ---- stage 4: tensor product + v4-red scatter ----
        {
            float e0v[8];
            e0v[0] = F0a.x; e0v[1] = F0a.y; e0v[2] = F0a.z; e0v[3] = F0a.w;
            e0v[4] = F0b.x; e0v[5] = F0b.y; e0v[6] = F0b.z; e0v[7] = F0b.w;
            float e1v[24];
#pragma unroll
            for (int i = 0; i < 6; i++) {
                e1v[4 * i + 0] = F1[i].x; e1v[4 * i + 1] = F1[i].y;
                e1v[4 * i + 2] = F1[i].z; e1v[4 * i + 3] = F1[i].w;
            }
            float w0v[8], w1v[8], w2v[8], w3v[8];
#pragma unroll
            for (int x = 0; x < 8; x += 4) {
                float4 v;
                v = *(const float4*)&sWW[e4 * 132 + 0  + u0 + x]; w0v[x] = v.x; w0v[x+1] = v.y; w0v[x+2] = v.z; w0v[x+3] = v.w;
                v = *(const float4*)&sWW[e4 * 132 + 32 + u0 + x]; w1v[x] = v.x; w1v[x+1] = v.y; w1v[x+2] = v.z; w1v[x+3] = v.w;
                v = *(const float4*)&sWW[e4 * 132 + 64 + u0 + x]; w2v[x] = v.x; w2v[x+1] = v.y; w2v[x+2] = v.z; w2v[x+3] = v.w;
                v = *(const float4*)&sWW[e4 * 132 + 96 + u0 + x]; w3v[x] = v.x; w3v[x+1] = v.y; w3v[x+2] = v.z; w3v[x+3] = v.w;
            }
            const float inn = 0.25f;
            const float k3  = 0.5773502691896258f * 0.25f;
            float p0[8], p3[8], p1[24], p2[24];
#pragma unroll
            for (int x = 0; x < 8; x++) {
                float e0u = e0v[x];
                float ex = e1v[3 * x + 0], ey = e1v[3 * x + 1], ez = e1v[3 * x + 2];
                p0[x] = w0v[x] * e0u * s0 * inn;
                p3[x] = w3v[x] * (ex * s1x + ey * s1y + ez * s1z) * k3;
                float w1e = w1v[x] * e0u * inn;
                p1[3 * x + 0] = w1e * s1x; p1[3 * x + 1] = w1e * s1y; p1[3 * x + 2] = w1e * s1z;
                float w2s = w2v[x] * s0 * inn;
                p2[3 * x + 0] = w2s * ex; p2[3 * x + 1] = w2s * ey; p2[3 * x + 2] = w2s * ez;
            }
            float* n0a = &g_n0[dst * 64 + u0];
            red_add_v4(n0a,     p0[0], p0[1], p0[2], p0[3]);
            red_add_v4(n0a + 4, p0[4], p0[5], p0[6], p0[7]);
            float* n0b = &g_n0[dst * 64 + 32 + u0];
            red_add_v4(n0b,     p3[0], p3[1], p3[2], p3[3]);
            red_add_v4(n0b + 4, p3[4], p3[5], p3[6], p3[7]);
            float* n1a = &g_n1[dst * 192 + u0 * 3];
#pragma unroll
            for (int i = 0; i < 6; i++)
                red_add_v4(n1a + 4 * i, p1[4 * i], p1[4 * i + 1], p1[4 * i + 2], p1[4 * i + 3]);
            float* n1b = &g_n1[dst * 192 + 96 + u0 * 3];
#pragma unroll
            for (int i = 0; i < 6; i++)
                red_add_v4(n1b + 4 * i, p2[4 * i], p2[4 * i + 1], p2[4 * i + 2], p2[4 * i + 3]);
        }
        __syncwarp(); // protect sWW/sES before next group's writes
    }
}

// ---------------- kernel 3: output transform (8 nodes/block, direct global reads) ----------------
__global__ __launch_bounds__(256) void output_kernel(
    const float* __restrict__ Wout0, const float* __restrict__ Wout1,
    float* __restrict__ out)
{
    __shared__ float sW0T[32 * 68], sW1T[32 * 68];  // j-major transposed, pad 4
    int t = threadIdx.x;
    for (int i = t; i < FC * MUL; i += 256) {
        int u = i >> 5, j = i & 31;
        sW0T[j * 68 + u] = Wout0[i];
        sW1T[j * 68 + u] = Wout1[i];
    }
    __syncthreads();

    int ni = t >> 5, j = t & 31;
    int n = blockIdx.x * 8 + ni;
    const float4* N0 = (const float4*)&g_n0[n * 64];
    const float4* N1 = (const float4*)&g_n1[n * 192];

    float c0 = 0.f, c1x = 0.f, c1y = 0.f, c1z = 0.f;
#pragma unroll
    for (int uu = 0; uu < 16; uu++) {
        int u = uu * 4;
        float4 w0 = *(const float4*)&sW0T[j * 68 + u];
        float4 n0 = __ldg(&N0[uu]);
        c0 = fmaf(w0.x, n0.x, fmaf(w0.y, n0.y, fmaf(w0.z, n0.z, fmaf(w0.w, n0.w, c0))));
        float4 w1 = *(const float4*)&sW1T[j * 68 + u];
        float4 v0 = __ldg(&N1[3 * uu + 0]);
        float4 v1 = __ldg(&N1[3 * uu + 1]);
        float4 v2 = __ldg(&N1[3 * uu + 2]);
        c1x = fmaf(w1.x, v0.x, fmaf(w1.y, v0.w, fmaf(w1.z, v1.z, fmaf(w1.w, v2.y, c1x))));
        c1y = fmaf(w1.x, v0.y, fmaf(w1.y, v1.x, fmaf(w1.z, v1.w, fmaf(w1.w, v2.z, c1y))));
        c1z = fmaf(w1.x, v0.z, fmaf(w1.y, v1.y, fmaf(w1.z, v2.x, fmaf(w1.w, v2.w, c1z))));
    }
    const float i2m = 0.125f;
    const float cc = 0.9238795325112867f;
    const float ss = 0.3826834323650898f;
    int vb = (n * 32 + j) * 3;
    float o0  = cc * __ldg(&g_self0[n * 32 + j]) + ss * c0 * i2m;
    float o1x = cc * __ldg(&g_self1[vb + 0]) + ss * c1x * i2m;
    float o1y = cc * __ldg(&g_self1[vb + 1]) + ss * c1y * i2m;
    float o1z = cc * __ldg(&g_self1[vb + 2]) + ss * c1z * i2m;
    out[n * 128 + j] = o0;
    out[n * 128 + 32 + j * 3 + 0] = o1x;
    out[n * 128 + 32 + j * 3 + 1] = o1y;
    out[n * 128 + 32 + j * 3 + 2] = o1z;
}

// ---------------- host launcher ----------------
extern "C" void kernel_launch(void* const* d_in, const int* in_sizes, int n_in,
                              void* d_out, int out_size)
{
    const float* node_s      = (const float*)d_in[0];
    const float* node_v      = (const float*)d_in[1];
    const float* sh0         = (const float*)d_in[2];
    const float* sh1         = (const float*)d_in[3];
    const float* edge_scalar = (const float*)d_in[4];
    const int*   edge_src    = (const int*)d_in[5];
    const int*   edge_dst    = (const int*)d_in[6];
    const float* W_feat0     = (const float*)d_in[7];
    const float* W_self0     = (const float*)d_in[8];
    const float* W_feat1     = (const float*)d_in[9];
    const float* W_self1     = (const float*)d_in[10];
    const float* mlp_w0      = (const float*)d_in[11];
    const float* mlp_w1      = (const float*)d_in[12];
    const float* wp0         = (const float*)d_in[13];
    const float* wp1         = (const float*)d_in[14];
    const float* wp2         = (const float*)d_in[15];
    const float* wp3         = (const float*)d_in[16];
    const float* W_out0      = (const float*)d_in[17];
    const float* W_out1      = (const float*)d_in[18];
    float* out = (float*)d_out;

    cudaFuncSetAttribute(edge_kernel, cudaFuncAttributeMaxDynamicSharedMemorySize,
                         EDGE_SMEM_BYTES);

    zero_acc_kernel<<<(N_NODES * 48 + 255) / 256, 256>>>();

    node_transform_kernel<<<N_NODES / 4, 128>>>(node_s, node_v,
                                                W_feat0, W_self0, W_feat1, W_self1);

    edge_kernel<<<EDGE_BLOCKS, 512, EDGE_SMEM_BYTES>>>(
        sh0, sh1, edge_scalar, edge_src, edge_dst,
        mlp_w0, mlp_w1, wp0, wp1, wp2, wp3);

    output_kernel<<<N_NODES / 8, 256>>>(W_out0, W_out1, out);
}

// round 5
// speedup vs baseline: 1.2435x; 1.0016x over previous
#include <cuda_runtime.h>
#include <math.h>

#define N_NODES 50000
#define N_EDGES 800000
#define MUL 32
#define RAD 8
#define FC 64
#define EDGE_BLOCKS 148
#define N_GROUPS (N_EDGES / 8)   // 8 edges per warp-group

typedef unsigned long long u64;

// ---------------- scratch (static device globals; no allocation) ----------------
__device__ __align__(16) float g_f0[N_NODES * MUL];
__device__ __align__(16) float g_self0[N_NODES * MUL];
__device__ __align__(16) float g_f1[N_NODES * MUL * 3];
__device__ __align__(16) float g_self1[N_NODES * MUL * 3];
__device__ __align__(16) float g_n0[N_NODES * 2 * MUL];
__device__ __align__(16) float g_n1[N_NODES * 2 * MUL * 3];

__device__ __forceinline__ float gelu_f(float x) {
    float u = 0.7978845608028654f * fmaf(0.044715f * x, x * x, x);
    float t;
    asm("tanh.approx.f32 %0, %1;" : "=f"(t) : "f"(u));
    return 0.5f * x * (1.0f + t);
}

__device__ __forceinline__ u64 splat2(float v) {
    u64 r; asm("mov.b64 %0, {%1, %1};" : "=l"(r) : "f"(v)); return r;
}
__device__ __forceinline__ u64 ffma2(u64 a, u64 b, u64 c) {
    u64 d; asm("fma.rn.f32x2 %0, %1, %2, %3;" : "=l"(d) : "l"(a), "l"(b), "l"(c)); return d;
}
__device__ __forceinline__ float2 unpk2(u64 v) {
    float2 f; asm("mov.b64 {%0, %1}, %2;" : "=f"(f.x), "=f"(f.y) : "l"(v)); return f;
}

__device__ __forceinline__ void red_add_v4(float* addr, float a, float b, float c, float d) {
    asm volatile("red.global.add.v4.f32 [%0], {%1,%2,%3,%4};"
                 :: "l"(addr), "f"(a), "f"(b), "f"(c), "f"(d) : "memory");
}

// ---------------- kernel 0: zero accumulators ----------------
__global__ void zero_acc_kernel() {
    int i = blockIdx.x * blockDim.x + threadIdx.x;
    float4 z = make_float4(0.f, 0.f, 0.f, 0.f);
    if (i < N_NODES * 16) reinterpret_cast<float4*>(g_n0)[i] = z;
    if (i < N_NODES * 48) reinterpret_cast<float4*>(g_n1)[i] = z;
}

// ---------------- kernel 1: node pre-transform ----------------
__global__ __launch_bounds__(128) void node_transform_kernel(
    const float* __restrict__ node_s, const float* __restrict__ node_v,
    const float* __restrict__ Wf0, const float* __restrict__ Ws0,
    const float* __restrict__ Wf1, const float* __restrict__ Ws1)
{
    __shared__ float sWf0[MUL * MUL], sWs0[MUL * MUL], sWf1[MUL * MUL], sWs1[MUL * MUL];
    __shared__ float sS[4][MUL];
    __shared__ float sV[4][MUL * 3];
    int t = threadIdx.x;
    for (int i = t; i < MUL * MUL; i += 128) {
        sWf0[i] = Wf0[i]; sWs0[i] = Ws0[i]; sWf1[i] = Wf1[i]; sWs1[i] = Ws1[i];
    }
    int node0 = blockIdx.x * 4;
    int ni = t >> 5, j = t & 31;
    int n = node0 + ni;
    sS[ni][j] = node_s[n * MUL + j];
#pragma unroll
    for (int i = 0; i < 3; i++) sV[ni][j * 3 + i] = node_v[n * MUL * 3 + j * 3 + i];
    __syncthreads();

    float a0 = 0.f, b0 = 0.f;
    float a1x = 0.f, a1y = 0.f, a1z = 0.f, b1x = 0.f, b1y = 0.f, b1z = 0.f;
#pragma unroll
    for (int u = 0; u < MUL; ++u) {
        float su = sS[ni][u];
        float vx = sV[ni][u * 3 + 0], vy = sV[ni][u * 3 + 1], vz = sV[ni][u * 3 + 2];
        float wf0 = sWf0[u * MUL + j], ws0 = sWs0[u * MUL + j];
        float wf1 = sWf1[u * MUL + j], ws1 = sWs1[u * MUL + j];
        a0 += su * wf0;  b0 += su * ws0;
        a1x += vx * wf1; a1y += vy * wf1; a1z += vz * wf1;
        b1x += vx * ws1; b1y += vy * ws1; b1z += vz * ws1;
    }
    const float ism = 0.17677669529663687f;
    g_f0[n * MUL + j]    = a0 * ism;
    g_self0[n * MUL + j] = b0 * ism;
    int vb = (n * MUL + j) * 3;
    g_f1[vb + 0] = a1x * ism; g_f1[vb + 1] = a1y * ism; g_f1[vb + 2] = a1z * ism;
    g_self1[vb + 0] = b1x * ism; g_self1[vb + 1] = b1y * ism; g_self1[vb + 2] = b1z * ism;
}

// ---------------- kernel 2: edge pipeline, 16 independent warps per CTA ----------------
// smem (floats):
//   weights: sW0 [8][64] @0 (512) ; sW1v [16][260] @512 (4160) ; sWPv [16][516] @4672 (8256)
//   per-warp slice @12928 + wid*2208:
//     sH1 [8][68] (544) ; sH2 [8][68] (544) ; sWW [8][132] (1056) ; sES [8][8] (64)
#define EDGE_SMEM_FLOATS (12928 + 16 * 2208)
#define EDGE_SMEM_BYTES  (EDGE_SMEM_FLOATS * 4)

__global__ __launch_bounds__(512, 1) void edge_kernel(
    const float* __restrict__ sh0, const float* __restrict__ sh1,
    const float* __restrict__ edge_scalar,
    const int* __restrict__ edge_src, const int* __restrict__ edge_dst,
    const float* __restrict__ mlp_w0, const float* __restrict__ mlp_w1,
    const float* __restrict__ wp0, const float* __restrict__ wp1,
    const float* __restrict__ wp2, const float* __restrict__ wp3)
{
    extern __shared__ float smem[];
    float* sW0  = smem;
    float* sW1v = smem + 512;
    float* sWPv = smem + 4672;

    int t = threadIdx.x;
    int wid = t >> 5, lane = t & 31;

    // ---- load weights once per block ----
    for (int i = t; i < RAD * FC; i += 512) sW0[i] = mlp_w0[i];
    for (int i = t; i < FC * FC; i += 512) {
        int k = i >> 6, j = i & 63;
        sW1v[(j >> 2) * 260 + k * 4 + (j & 3)] = mlp_w1[i];
    }
    for (int i = t; i < FC * MUL; i += 512) {
        int k = i >> 5, m = i & 31;
        int c;
        c = m;      sWPv[(c >> 3) * 516 + k * 8 + (c & 7)] = wp0[i];
        c = 32 + m; sWPv[(c >> 3) * 516 + k * 8 + (c & 7)] = wp1[i];
        c = 64 + m; sWPv[(c >> 3) * 516 + k * 8 + (c & 7)] = wp2[i];
        c = 96 + m; sWPv[(c >> 3) * 516 + k * 8 + (c & 7)] = wp3[i];
    }
    __syncthreads();

    float* sWarp = smem + 12928 + wid * 2208;
    float* sH1 = sWarp;
    float* sH2 = sWarp + 544;
    float* sWW = sWarp + 1088;
    float* sES = sWarp + 2144;

    const float isr = 0.35355339059327373f; // 1/sqrt(8)
    const float isf = 0.125f;               // 1/sqrt(64)

    int el = lane >> 4, jl = lane & 15;      // stages 1-3: edge group (4), col group
    int e4 = lane >> 2, q4 = lane & 3;       // stage 4: edge, quarter
    int u0 = q4 * 8;

    int gw = blockIdx.x * 16 + wid;
    int nw = gridDim.x * 16;

    for (int g = gw; g < N_GROUPS; g += nw) {
        int ebase = g * 8;

        // ---- load per-edge scalars (coalesced) + prefetch gathers ----
        *(float2*)&sES[lane * 2] = *(const float2*)&edge_scalar[ebase * RAD + lane * 2];

        int eg = ebase + e4;
        int src = edge_src[eg];
        int dst = edge_dst[eg];
        float s0  = sh0[eg];
        float s1x = sh1[eg * 3 + 0];
        float s1y = sh1[eg * 3 + 1];
        float s1z = sh1[eg * 3 + 2];
        float4 F0a = *(const float4*)&g_f0[src * 32 + u0];
        float4 F0b = *(const float4*)&g_f0[src * 32 + u0 + 4];
        float4 F1[6];
        {
            const float4* p = (const float4*)&g_f1[src * 96 + u0 * 3];
#pragma unroll
            for (int i = 0; i < 6; i++) F1[i] = p[i];
        }
        __syncwarp();

        // ---- stage 1: H1 = gelu(ES @ W0 * isr)  (8e x 64j, K=8) ----
        {
            u64 acc[4][2];
#pragma unroll
            for (int x = 0; x < 4; x++) { acc[x][0] = 0ULL; acc[x][1] = 0ULL; }
#pragma unroll
            for (int k = 0; k < RAD; k++) {
                ulonglong2 b = *(const ulonglong2*)&sW0[k * 64 + jl * 4];
#pragma unroll
                for (int x = 0; x < 4; x++) {
                    u64 as = splat2(sES[(el * 4 + x) * 8 + k]);
                    acc[x][0] = ffma2(as, b.x, acc[x][0]);
                    acc[x][1] = ffma2(as, b.y, acc[x][1]);
                }
            }
#pragma unroll
            for (int x = 0; x < 4; x++) {
                float2 lo = unpk2(acc[x][0]), hi = unpk2(acc[x][1]);
                float* row = &sH1[(el * 4 + x) * 68 + jl * 4];
                row[0] = gelu_f(lo.x * isr); row[1] = gelu_f(lo.y * isr);
                row[2] = gelu_f(hi.x * isr); row[3] = gelu_f(hi.y * isr);
            }
        }
        __syncwarp();

        // ---- stage 2: H2 = gelu(H1 @ W1 * isf)  (8e x 64j, K=64) ----
        {
            u64 acc[4][2];
#pragma unroll
            for (int x = 0; x < 4; x++) { acc[x][0] = 0ULL; acc[x][1] = 0ULL; }
#pragma unroll 4
            for (int kk = 0; kk < FC; kk += 4) {
                float4 a[4];
#pragma unroll
                for (int x = 0; x < 4; x++)
                    a[x] = *(const float4*)&sH1[(el * 4 + x) * 68 + kk];
                ulonglong2 b0 = *(const ulonglong2*)&sW1v[jl * 260 + (kk + 0) * 4];
                ulonglong2 b1 = *(const ulonglong2*)&sW1v[jl * 260 + (kk + 1) * 4];
                ulonglong2 b2 = *(const ulonglong2*)&sW1v[jl * 260 + (kk + 2) * 4];
                ulonglong2 b3 = *(const ulonglong2*)&sW1v[jl * 260 + (kk + 3) * 4];
#pragma unroll
                for (int x = 0; x < 4; x++) {
                    u64 a0 = splat2(a[x].x), a1 = splat2(a[x].y);
                    u64 a2 = splat2(a[x].z), a3 = splat2(a[x].w);
                    acc[x][0] = ffma2(a0, b0.x, acc[x][0]);
                    acc[x][1] = ffma2(a0, b0.y, acc[x][1]);
                    acc[x][0] = ffma2(a1, b1.x, acc[x][0]);
                    acc[x][1] = ffma2(a1, b1.y, acc[x][1]);
                    acc[x][0] = ffma2(a2, b2.x, acc[x][0]);
                    acc[x][1] = ffma2(a2, b2.y, acc[x][1]);
                    acc[x][0] = ffma2(a3, b3.x, acc[x][0]);
                    acc[x][1] = ffma2(a3, b3.y, acc[x][1]);
                }
            }
#pragma unroll
            for (int x = 0; x < 4; x++) {
                float2 lo = unpk2(acc[x][0]), hi = unpk2(acc[x][1]);
                float* row = &sH2[(el * 4 + x) * 68 + jl * 4];
                row[0] = gelu_f(lo.x * isf); row[1] = gelu_f(lo.y * isf);
                row[2] = gelu_f(hi.x * isf); row[3] = gelu_f(hi.y * isf);
            }
        }
        __syncwarp();

        // ---- stage 3: W = H2 @ [wp0..wp3] * isf  (8e x 128m, K=64) ----
        {
            u64 acc[4][4];
#pragma unroll
            for (int x = 0; x < 4; x++)
#pragma unroll
                for (int y = 0; y < 4; y++) acc[x][y] = 0ULL;
#pragma unroll 4
            for (int kk = 0; kk < FC; kk += 4) {
                float4 a[4];
#pragma unroll
                for (int x = 0; x < 4; x++)
                    a[x] = *(const float4*)&sH2[(el * 4 + x) * 68 + kk];
#pragma unroll
                for (int dk = 0; dk < 4; dk++) {
                    ulonglong2 c0 = *(const ulonglong2*)&sWPv[jl * 516 + (kk + dk) * 8];
                    ulonglong2 c1 = *(const ulonglong2*)&sWPv[jl * 516 + (kk + dk) * 8 + 4];
#pragma unroll
                    for (int x = 0; x < 4; x++) {
                        float av = (dk == 0) ? a[x].x : (dk == 1) ? a[x].y : (dk == 2) ? a[x].z : a[x].w;
                        u64 as = splat2(av);
                        acc[x][0] = ffma2(as, c0.x, acc[x][0]);
                        acc[x][1] = ffma2(as, c0.y, acc[x][1]);
                        acc[x][2] = ffma2(as, c1.x, acc[x][2]);
                        acc[x][3] = ffma2(as, c1.y, acc[x][3]);
                    }
                }
            }
#pragma unroll
            for (int x = 0; x < 4; x++) {
                float2 p0 = unpk2(acc[x][0]), p1 = unpk2(acc[x][1]);
                float2 p2 = unpk2(acc[x][2]), p3 = unpk2(acc[x][3]);
                float4 v0 = make_float4(p0.x * isf, p0.y * isf, p1.x * isf, p1.y * isf);
                float4 v1 = make_float4(p2.x * isf, p2.y * isf, p3.x * isf, p3.y * isf);
                *(float4*)&sWW[(el * 4 + x) * 132 + jl * 8]     = v0;
                *(float4*)&sWW[(el * 4 + x) * 132 + jl * 8 + 4] = v1;
            }
        }
        __syncwarp();

        // ---- stage 4: tensor product + v4-red scatter ----
        {
            float e0v[8];
            e0v[0] = F0a.x; e0v[1] = F0a.y; e0v[2] = F0a.z; e0v[3] = F0a.w;
            e0v[4] = F0b.x; e0v[5] = F0b.y; e0v[6] = F0b.z; e0v[7] = F0b.w;
            float e1v[24];
#pragma unroll
            for (int i = 0; i < 6; i++) {
                e1v[4 * i + 0] = F1[i].x; e1v[4 * i + 1] = F1[i].y;
                e1v[4 * i + 2] = F1[i].z; e1v[4 * i + 3] = F1[i].w;
            }
            float w0v[8], w1v[8], w2v[8], w3v[8];
#pragma unroll
            for (int x = 0; x < 8; x += 4) {
                float4 v;
                v = *(const float4*)&sWW[e4 * 132 + 0  + u0 + x]; w0v[x] = v.x; w0v[x+1] = v.y; w0v[x+2] = v.z; w0v[x+3] = v.w;
                v = *(const float4*)&sWW[e4 * 132 + 32 + u0 + x]; w1v[x] = v.x; w1v[x+1] = v.y; w1v[x+2] = v.z; w1v[x+3] = v.w;
                v = *(const float4*)&sWW[e4 * 132 + 64 + u0 + x]; w2v[x] = v.x; w2v[x+1] = v.y; w2v[x+2] = v.z; w2v[x+3] = v.w;
                v = *(const float4*)&sWW[e4 * 132 + 96 + u0 + x]; w3v[x] = v.x; w3v[x+1] = v.y; w3v[x+2] = v.z; w3v[x+3] = v.w;
            }
            const float inn = 0.25f;
            const float k3  = 0.5773502691896258f * 0.25f;
            float p0[8], p3[8], p1[24], p2[24];
#pragma unroll
            for (int x = 0; x < 8; x++) {
                float e0u = e0v[x];
                float ex = e1v[3 * x + 0], ey = e1v[3 * x + 1], ez = e1v[3 * x + 2];
                p0[x] = w0v[x] * e0u * s0 * inn;
                p3[x] = w3v[x] * (ex * s1x + ey * s1y + ez * s1z) * k3;
                float w1e = w1v[x] * e0u * inn;
                p1[3 * x + 0] = w1e * s1x; p1[3 * x + 1] = w1e * s1y; p1[3 * x + 2] = w1e * s1z;
                float w2s = w2v[x] * s0 * inn;
                p2[3 * x + 0] = w2s * ex; p2[3 * x + 1] = w2s * ey; p2[3 * x + 2] = w2s * ez;
            }
            float* n0a = &g_n0[dst * 64 + u0];
            red_add_v4(n0a,     p0[0], p0[1], p0[2], p0[3]);
            red_add_v4(n0a + 4, p0[4], p0[5], p0[6], p0[7]);
            float* n0b = &g_n0[dst * 64 + 32 + u0];
            red_add_v4(n0b,     p3[0], p3[1], p3[2], p3[3]);
            red_add_v4(n0b + 4, p3[4], p3[5], p3[6], p3[7]);
            float* n1a = &g_n1[dst * 192 + u0 * 3];
#pragma unroll
            for (int i = 0; i < 6; i++)
                red_add_v4(n1a + 4 * i, p1[4 * i], p1[4 * i + 1], p1[4 * i + 2], p1[4 * i + 3]);
            float* n1b = &g_n1[dst * 192 + 96 + u0 * 3];
#pragma unroll
            for (int i = 0; i < 6; i++)
                red_add_v4(n1b + 4 * i, p2[4 * i], p2[4 * i + 1], p2[4 * i + 2], p2[4 * i + 3]);
        }
        __syncwarp(); // protect sWW/sES before next group's writes
    }
}

// ---------------- kernel 3: output transform (8 nodes/block, direct global reads) ----------------
__global__ __launch_bounds__(256) void output_kernel(
    const float* __restrict__ Wout0, const float* __restrict__ Wout1,
    float* __restrict__ out)
{
    __shared__ float sW0T[32 * 68], sW1T[32 * 68];  // j-major transposed, pad 4
    int t = threadIdx.x;
    for (int i = t; i < FC * MUL; i += 256) {
        int u = i >> 5, j = i & 31;
        sW0T[j * 68 + u] = Wout0[i];
        sW1T[j * 68 + u] = Wout1[i];
    }
    __syncthreads();

    int ni = t >> 5, j = t & 31;
    int n = blockIdx.x * 8 + ni;
    const float4* N0 = (const float4*)&g_n0[n * 64];
    const float4* N1 = (const float4*)&g_n1[n * 192];

    float c0 = 0.f, c1x = 0.f, c1y = 0.f, c1z = 0.f;
#pragma unroll
    for (int uu = 0; uu < 16; uu++) {
        int u = uu * 4;
        float4 w0 = *(const float4*)&sW0T[j * 68 + u];
        float4 n0 = __ldg(&N0[uu]);
        c0 = fmaf(w0.x, n0.x, fmaf(w0.y, n0.y, fmaf(w0.z, n0.z, fmaf(w0.w, n0.w, c0))));
        float4 w1 = *(const float4*)&sW1T[j * 68 + u];
        float4 v0 = __ldg(&N1[3 * uu + 0]);
        float4 v1 = __ldg(&N1[3 * uu + 1]);
        float4 v2 = __ldg(&N1[3 * uu + 2]);
        c1x = fmaf(w1.x, v0.x, fmaf(w1.y, v0.w, fmaf(w1.z, v1.z, fmaf(w1.w, v2.y, c1x))));
        c1y = fmaf(w1.x, v0.y, fmaf(w1.y, v1.x, fmaf(w1.z, v1.w, fmaf(w1.w, v2.z, c1y))));
        c1z = fmaf(w1.x, v0.z, fmaf(w1.y, v1.y, fmaf(w1.z, v2.x, fmaf(w1.w, v2.w, c1z))));
    }
    const float i2m = 0.125f;
    const float cc = 0.9238795325112867f;
    const float ss = 0.3826834323650898f;
    int vb = (n * 32 + j) * 3;
    float o0  = cc * __ldg(&g_self0[n * 32 + j]) + ss * c0 * i2m;
    float o1x = cc * __ldg(&g_self1[vb + 0]) + ss * c1x * i2m;
    float o1y = cc * __ldg(&g_self1[vb + 1]) + ss * c1y * i2m;
    float o1z = cc * __ldg(&g_self1[vb + 2]) + ss * c1z * i2m;
    out[n * 128 + j] = o0;
    out[n * 128 + 32 + j * 3 + 0] = o1x;
    out[n * 128 + 32 + j * 3 + 1] = o1y;
    out[n * 128 + 32 + j * 3 + 2] = o1z;
}

// ---------------- host launcher ----------------
extern "C" void kernel_launch(void* const* d_in, const int* in_sizes, int n_in,
                              void* d_out, int out_size)
{
    const float* node_s      = (const float*)d_in[0];
    const float* node_v      = (const float*)d_in[1];
    const float* sh0         = (const float*)d_in[2];
    const float* sh1         = (const float*)d_in[3];
    const float* edge_scalar = (const float*)d_in[4];
    const int*   edge_src    = (const int*)d_in[5];
    const int*   edge_dst    = (const int*)d_in[6];
    const float* W_feat0     = (const float*)d_in[7];
    const float* W_self0     = (const float*)d_in[8];
    const float* W_feat1     = (const float*)d_in[9];
    const float* W_self1     = (const float*)d_in[10];
    const float* mlp_w0      = (const float*)d_in[11];
    const float* mlp_w1      = (const float*)d_in[12];
    const float* wp0         = (const float*)d_in[13];
    const float* wp1         = (const float*)d_in[14];
    const float* wp2         = (const float*)d_in[15];
    const float* wp3         = (const float*)d_in[16];
    const float* W_out0      = (const float*)d_in[17];
    const float* W_out1      = (const float*)d_in[18];
    float* out = (float*)d_out;

    cudaFuncSetAttribute(edge_kernel, cudaFuncAttributeMaxDynamicSharedMemorySize,
                         EDGE_SMEM_BYTES);

    zero_acc_kernel<<<(N_NODES * 48 + 255) / 256, 256>>>();

    node_transform_kernel<<<N_NODES / 4, 128>>>(node_s, node_v,
                                                W_feat0, W_self0, W_feat1, W_self1);

    edge_kernel<<<EDGE_BLOCKS, 512, EDGE_SMEM_BYTES>>>(
        sh0, sh1, edge_scalar, edge_src, edge_dst,
        mlp_w0, mlp_w1, wp0, wp1, wp2, wp3);

    output_kernel<<<N_NODES / 8, 256>>>(W_out0, W_out1, out);
}